// round 6
// baseline (speedup 1.0000x reference)
#include <cuda_runtime.h>
#include <math_constants.h>

// Fixed shapes
#define B    32
#define H    8192
#define HO   4096
#define W4   64            // 256 floats / 4
#define CH   32            // output rows per thread in K1
#define SUBS 4
#define CHUNKGROUPS 32     // (HO/CH)/SUBS

#define K2_GPB  64         // K2 blocks per batch
#define K2_ROWS (HO / K2_GPB)   // 64 rows per K2 block
#define K2_F4   (K2_ROWS * W4)  // 4096 float4 per K2 block
#define K2_IT   (K2_F4 / 256)   // 16 float4 per thread

// Per-batch min/max, encoded order-preserving uint32.
// Static-initialized; K2's last block per batch resets for the next replay.
__device__ unsigned g_min[B] = {
    0xFFFFFFFFu,0xFFFFFFFFu,0xFFFFFFFFu,0xFFFFFFFFu,0xFFFFFFFFu,0xFFFFFFFFu,0xFFFFFFFFu,0xFFFFFFFFu,
    0xFFFFFFFFu,0xFFFFFFFFu,0xFFFFFFFFu,0xFFFFFFFFu,0xFFFFFFFFu,0xFFFFFFFFu,0xFFFFFFFFu,0xFFFFFFFFu,
    0xFFFFFFFFu,0xFFFFFFFFu,0xFFFFFFFFu,0xFFFFFFFFu,0xFFFFFFFFu,0xFFFFFFFFu,0xFFFFFFFFu,0xFFFFFFFFu,
    0xFFFFFFFFu,0xFFFFFFFFu,0xFFFFFFFFu,0xFFFFFFFFu,0xFFFFFFFFu,0xFFFFFFFFu,0xFFFFFFFFu,0xFFFFFFFFu};
__device__ unsigned g_max[B];   // zero-init == encoded -inf
__device__ int g_done2[B];      // zero-init; K2 per-batch completion counter

__device__ __forceinline__ unsigned enc_f(float f) {
    unsigned u = __float_as_uint(f);
    return (u & 0x80000000u) ? ~u : (u | 0x80000000u);
}
__device__ __forceinline__ float dec_f(unsigned e) {
    unsigned u = (e & 0x80000000u) ? (e ^ 0x80000000u) : ~e;
    return __uint_as_float(u);
}

// K1: pool along H (k=3,s=2,pad=1). Write un-normalized pooled values to out
// (writeback stores -> dirty lines parked in L2), publish per-batch min/max.
__global__ __launch_bounds__(256, 4)
void pool_kernel(const float4* __restrict__ x, float4* __restrict__ out) {
    const int b    = blockIdx.x;
    const int w4   = threadIdx.x & (W4 - 1);
    const int sub  = threadIdx.x >> 6;                 // 0..3
    const int chunk = blockIdx.y * SUBS + sub;         // 0..127
    const int h0   = chunk * CH;                       // first output row

    const float4* __restrict__ xb = x + (size_t)b * H * W4;
    float4* __restrict__ ob = out + (size_t)b * HO * W4;

    float4 prev;
    if (h0 == 0) {
        prev = make_float4(-CUDART_INF_F, -CUDART_INF_F, -CUDART_INF_F, -CUDART_INF_F);
    } else {
        prev = __ldcs(&xb[(size_t)(2 * h0 - 1) * W4 + w4]);
    }

    float mn =  CUDART_INF_F;
    float mx = -CUDART_INF_F;

    int hin = 2 * h0;
    #pragma unroll 8
    for (int i = 0; i < CH; i++) {
        float4 a = __ldcs(&xb[(size_t)hin * W4 + w4]);
        float4 c = __ldcs(&xb[(size_t)(hin + 1) * W4 + w4]);
        float4 p;
        p.x = fmaxf(fmaxf(a.x, c.x), prev.x);
        p.y = fmaxf(fmaxf(a.y, c.y), prev.y);
        p.z = fmaxf(fmaxf(a.z, c.z), prev.z);
        p.w = fmaxf(fmaxf(a.w, c.w), prev.w);
        ob[(size_t)(h0 + i) * W4 + w4] = p;            // writeback: park in L2
        mn = fminf(mn, fminf(fminf(p.x, p.y), fminf(p.z, p.w)));
        mx = fmaxf(mx, fmaxf(fmaxf(p.x, p.y), fmaxf(p.z, p.w)));
        prev = c;
        hin += 2;
    }

    // Warp reduce
    #pragma unroll
    for (int off = 16; off > 0; off >>= 1) {
        mn = fminf(mn, __shfl_xor_sync(0xFFFFFFFFu, mn, off));
        mx = fmaxf(mx, __shfl_xor_sync(0xFFFFFFFFu, mx, off));
    }
    __shared__ float s_mn[8], s_mx[8];
    const int lane = threadIdx.x & 31;
    const int wid  = threadIdx.x >> 5;
    if (lane == 0) { s_mn[wid] = mn; s_mx[wid] = mx; }
    __syncthreads();
    if (wid == 0) {
        mn = (lane < 8) ? s_mn[lane] :  CUDART_INF_F;
        mx = (lane < 8) ? s_mx[lane] : -CUDART_INF_F;
        #pragma unroll
        for (int off = 4; off > 0; off >>= 1) {
            mn = fminf(mn, __shfl_xor_sync(0xFFFFFFFFu, mn, off));
            mx = fmaxf(mx, __shfl_xor_sync(0xFFFFFFFFu, mx, off));
        }
        if (lane == 0) {
            atomicMin(&g_min[b], enc_f(mn));
            atomicMax(&g_max[b], enc_f(mx));
        }
    }
}

// K2: in-place normalize, reverse batch order (consume L2-resident tail first).
// Last finishing block of each batch resets that batch's state for next replay.
__global__ __launch_bounds__(256, 8)
void norm_kernel(float4* __restrict__ out) {
    const int blk = blockIdx.x;
    const int bb  = (B - 1) - (blk >> 6);        // reverse batch order
    const int g2  = blk & (K2_GPB - 1);
    const int tid = threadIdx.x;

    const float mnv = dec_f(g_min[bb]);
    const float mxv = dec_f(g_max[bb]);
    const float inv = 1.0f / (mxv - mnv);

    float4* __restrict__ p = out + (size_t)bb * HO * W4 + (size_t)g2 * K2_F4;

    #pragma unroll
    for (int i = 0; i < K2_IT; i++) {
        const int idx = i * 256 + tid;
        float4 v = p[idx];
        v.x = (v.x - mnv) * inv;
        v.y = (v.y - mnv) * inv;
        v.z = (v.z - mnv) * inv;
        v.w = (v.w - mnv) * inv;
        p[idx] = v;
    }

    // Self-reset for next graph replay.
    __syncthreads();
    if (tid == 0) {
        int d = atomicAdd(&g_done2[bb], 1);
        if (d == K2_GPB - 1) {
            *(volatile unsigned*)&g_min[bb] = 0xFFFFFFFFu;
            *(volatile unsigned*)&g_max[bb] = 0x00000000u;
            *(volatile int*)&g_done2[bb] = 0;
            __threadfence();
        }
    }
}

extern "C" void kernel_launch(void* const* d_in, const int* in_sizes, int n_in,
                              void* d_out, int out_size) {
    (void)in_sizes; (void)n_in; (void)out_size;
    const float4* x = (const float4*)d_in[0];
    float4* out = (float4*)d_out;

    dim3 grid1(B, CHUNKGROUPS);              // 32 x 32 = 1024 blocks
    pool_kernel<<<grid1, 256>>>(x, out);

    norm_kernel<<<B * K2_GPB, 256>>>(out);   // 2048 blocks
}